// round 3
// baseline (speedup 1.0000x reference)
#include <cuda_runtime.h>
#include <math.h>

// Problem constants
#define Bn 2
#define Cn 256
#define Hn 96
#define Wn 96
#define HW (Hn*Wn)          // 9216
#define CGn 64
#define KKn 9

// Output layout (tuple order, each tensor flattened C-order)
#define OUT_LOGITS 0                       // [2,1,96,96]
#define OUT_BBOX   18432                   // [2,4,96,96]
#define OUT_SHAPE  92160                   // [2,2,96,96]
#define OUT_LOC    129024                  // [2,1,96,96]

#define AS_STRIDE 66                       // padded: conflict-free gather stores

typedef unsigned long long u64;

// Scratch (device globals; no dynamic allocation allowed)
__device__ float g_x  [Bn*HW*Cn];      // feature NHWC
__device__ float g_t  [Bn*HW*Cn];      // conv1 output NHWC
__device__ float g_off[Bn*HW*72];      // per-pixel offsets
__device__ float g_w1 [KKn*Cn*Cn];     // conv_w  -> [tap][cin][cout]
__device__ float g_w2 [KKn*Cn*Cn];     // adapt_w -> [(g*9+tap)][ci(64)][cout]

// ---- packed fp32x2 helpers -------------------------------------------------
__device__ __forceinline__ u64 pk2(float lo, float hi) {
    u64 r; asm("mov.b64 %0, {%1,%2};" : "=l"(r) : "f"(lo), "f"(hi)); return r;
}
__device__ __forceinline__ void up2(u64 v, float& lo, float& hi) {
    asm("mov.b64 {%0,%1}, %2;" : "=f"(lo), "=f"(hi) : "l"(v));
}
__device__ __forceinline__ void fma2(u64& d, u64 a, u64 b) {
    asm("fma.rn.f32x2 %0, %1, %2, %0;" : "+l"(d) : "l"(a), "l"(b));
}

// ---------------------------------------------------------------------------
// Kernel 1: NCHW -> NHWC transpose of feature
// ---------------------------------------------------------------------------
__global__ void k_transpose_feat(const float* __restrict__ x) {
    __shared__ float tile[32][33];
    int b  = blockIdx.z;
    int p0 = blockIdx.x * 32;
    int c0 = blockIdx.y * 32;
    int txi = threadIdx.x, tyi = threadIdx.y;  // 32 x 8
    #pragma unroll
    for (int s = 0; s < 32; s += 8)
        tile[tyi + s][txi] = x[(size_t)(b*Cn + c0 + tyi + s)*HW + p0 + txi];
    __syncthreads();
    #pragma unroll
    for (int s = 0; s < 32; s += 8)
        g_x[(size_t)(b*HW + p0 + tyi + s)*Cn + c0 + txi] = tile[txi][tyi + s];
}

// ---------------------------------------------------------------------------
// Kernel 2: weight re-layout
// ---------------------------------------------------------------------------
__global__ void k_prep_w(const float* __restrict__ conv_w,
                         const float* __restrict__ adapt_w) {
    const int n = KKn*Cn*Cn;
    int idx = blockIdx.x * blockDim.x + threadIdx.x;
    if (idx < n) {
        int o   = idx & 255;
        int c   = (idx >> 8) & 255;
        int tap = idx >> 16;
        g_w1[idx] = conv_w[(o*Cn + c)*KKn + tap];
    } else if (idx < 2*n) {
        int j   = idx - n;
        int o   = j & 255;
        int row = j >> 8;
        int ci  = row & 63;
        int gt  = row >> 6;
        int g   = gt / 9, tap = gt % 9;
        g_w2[j] = adapt_w[(o*Cn + g*CGn + ci)*KKn + tap];
    }
}

// ---------------------------------------------------------------------------
// Shared GEMM micro-kernel piece (macro'd by inclusion of identical code):
// lane = tid&31 spans pixels (2 px/lane, px = lane*2 + {0,1})
// wg   = tid>>5 spans oc group (32 oc = 16 oc-pairs per warp)
// B smem reads are warp-uniform broadcasts; A reads dense LDS.64.
// ---------------------------------------------------------------------------

// ---------------------------------------------------------------------------
// Kernel 3: conv3x3 implicit GEMM (f32x2, double buffered) + fused heads
// ---------------------------------------------------------------------------
__global__ void __launch_bounds__(256, 2)
k_conv1(const float* __restrict__ conv_b_,
        const float* __restrict__ loc_w,  const float* __restrict__ loc_b,
        const float* __restrict__ shape_w,const float* __restrict__ shape_b,
        const float* __restrict__ offset_w,
        float* __restrict__ out) {
    __shared__ float As[2][16*AS_STRIDE];
    __shared__ float Bs[2][16*256];
    __shared__ float sh_s[64][2];

    const int b  = blockIdx.z;
    const int x0 = blockIdx.x * 16;
    const int y0 = blockIdx.y * 4;
    const int tid = threadIdx.x;
    const int lane = tid & 31;     // 2 px each -> 64 px
    const int wg   = tid >> 5;     // 32 oc each -> 256 oc

    // A gather mapping: pixel = tid>>2 (64), laneA = tid&3 (16ch/4)
    const int pA = tid >> 2, laneA = tid & 3;
    const int rowA = pA >> 4, colA = pA & 15;
    // B load mapping
    const int oB = (tid & 63) * 4, cB = tid >> 6;

    u64 acc[2][16];
    #pragma unroll
    for (int i = 0; i < 2; ++i)
        #pragma unroll
        for (int j = 0; j < 16; ++j) acc[i][j] = 0ull;

    float4 a4; float4 b4[4];

    // prologue: chunk 0 -> buffer 0
    {
        const int yy = y0 + rowA - 1, xx = x0 + colA - 1;
        a4 = make_float4(0.f, 0.f, 0.f, 0.f);
        if (yy >= 0 && yy < Hn && xx >= 0 && xx < Wn)
            a4 = *(const float4*)&g_x[((size_t)((b*Hn + yy)*Wn + xx))*Cn + laneA*4];
        #pragma unroll
        for (int q = 0; q < 4; ++q)
            b4[q] = *(const float4*)&g_w1[(size_t)(cB + q*4)*Cn + oB];
        As[0][(laneA*4+0)*AS_STRIDE + pA] = a4.x;
        As[0][(laneA*4+1)*AS_STRIDE + pA] = a4.y;
        As[0][(laneA*4+2)*AS_STRIDE + pA] = a4.z;
        As[0][(laneA*4+3)*AS_STRIDE + pA] = a4.w;
        #pragma unroll
        for (int q = 0; q < 4; ++q)
            *(float4*)&Bs[0][(cB + q*4)*256 + oB] = b4[q];
    }
    __syncthreads();

    for (int kt = 0; kt < 144; ++kt) {
        const int buf = kt & 1;
        if (kt < 143) {
            const int n   = kt + 1;
            const int tap = n >> 4, cc = (n & 15) << 4;
            const int dy  = tap/3 - 1, dx = tap%3 - 1;
            const int yy = y0 + rowA + dy, xx = x0 + colA + dx;
            a4 = make_float4(0.f, 0.f, 0.f, 0.f);
            if (yy >= 0 && yy < Hn && xx >= 0 && xx < Wn)
                a4 = *(const float4*)&g_x[((size_t)((b*Hn + yy)*Wn + xx))*Cn + cc + laneA*4];
            #pragma unroll
            for (int q = 0; q < 4; ++q)
                b4[q] = *(const float4*)&g_w1[(size_t)(tap*Cn + cc + cB + q*4)*Cn + oB];
        }

        #pragma unroll
        for (int kk = 0; kk < 16; ++kk) {
            float2 af = *(const float2*)&As[buf][kk*AS_STRIDE + lane*2];
            u64 ad0 = pk2(af.x, af.x);
            u64 ad1 = pk2(af.y, af.y);
            const u64* brow = (const u64*)&Bs[buf][kk*256 + wg*32];
            #pragma unroll
            for (int h = 0; h < 2; ++h) {
                u64 bb[8];
                #pragma unroll
                for (int j = 0; j < 8; ++j) bb[j] = brow[h*8 + j];
                #pragma unroll
                for (int j = 0; j < 8; ++j) {
                    fma2(acc[0][h*8+j], ad0, bb[j]);
                    fma2(acc[1][h*8+j], ad1, bb[j]);
                }
            }
        }

        if (kt < 143) {
            const int nb = (kt + 1) & 1;
            As[nb][(laneA*4+0)*AS_STRIDE + pA] = a4.x;
            As[nb][(laneA*4+1)*AS_STRIDE + pA] = a4.y;
            As[nb][(laneA*4+2)*AS_STRIDE + pA] = a4.z;
            As[nb][(laneA*4+3)*AS_STRIDE + pA] = a4.w;
            #pragma unroll
            for (int q = 0; q < 4; ++q)
                *(float4*)&Bs[nb][(cB + q*4)*256 + oB] = b4[q];
        }
        __syncthreads();
    }

    // ---- epilogue: bias + relu, write t, head partials -----------------
    float pl[2]  = {0.f, 0.f};
    float ps0[2] = {0.f, 0.f};
    float ps1[2] = {0.f, 0.f};

    #pragma unroll
    for (int i = 0; i < 2; ++i) {
        const int px  = lane*2 + i;
        const int y   = y0 + (px >> 4), xg = x0 + (px & 15);
        float* base = &g_t[((size_t)((b*Hn + y)*Wn + xg))*Cn + wg*32];
        #pragma unroll
        for (int j2 = 0; j2 < 8; ++j2) {     // pairs of oc-pairs -> float4
            float v[4];
            #pragma unroll
            for (int s = 0; s < 2; ++s) {
                const int j = j2*2 + s;
                float xlo, xhi; up2(acc[i][j], xlo, xhi);
                const int oc = wg*32 + 2*j;
                const float v0 = fmaxf(xlo + conv_b_[oc],   0.f);
                const float v1 = fmaxf(xhi + conv_b_[oc+1], 0.f);
                v[2*s]   = v0;
                v[2*s+1] = v1;
                pl[i]  += v0*loc_w[oc]          + v1*loc_w[oc+1];
                ps0[i] += v0*shape_w[oc]        + v1*shape_w[oc+1];
                ps1[i] += v0*shape_w[Cn+oc]     + v1*shape_w[Cn+oc+1];
            }
            *(float4*)&base[j2*4] = make_float4(v[0], v[1], v[2], v[3]);
        }
    }

    // cross-warp head reduction via smem (reuse Bs as scratch)
    float* red = &Bs[0][0];                  // 8192 floats available
    #pragma unroll
    for (int i = 0; i < 2; ++i) {
        const int px = lane*2 + i;
        red[0*512 + px*8 + wg] = pl[i];
        red[1*512 + px*8 + wg] = ps0[i];
        red[2*512 + px*8 + wg] = ps1[i];
    }
    __syncthreads();

    if (tid < 64) {
        const int px = tid;
        float sl = 0.f, s0 = 0.f, s1 = 0.f;
        #pragma unroll
        for (int w = 0; w < 8; ++w) {
            sl += red[0*512 + px*8 + w];
            s0 += red[1*512 + px*8 + w];
            s1 += red[2*512 + px*8 + w];
        }
        const int y = y0 + (px >> 4), xg = x0 + (px & 15);
        const int pix = y*Wn + xg;
        out[OUT_LOC + b*HW + pix] = sl + loc_b[0];
        const float a0 = s0 + shape_b[0];
        const float a1 = s1 + shape_b[1];
        out[OUT_SHAPE + (b*2 + 0)*HW + pix] = a0;
        out[OUT_SHAPE + (b*2 + 1)*HW + pix] = a1;
        sh_s[px][0] = a0;
        sh_s[px][1] = a1;
    }
    __syncthreads();

    // offsets: 64 px x 72 ch
    for (int idx = tid; idx < 64*72; idx += 256) {
        const int p = idx / 72, j = idx % 72;
        const int y = y0 + (p >> 4), xg = x0 + (p & 15);
        float v = sh_s[p][0] * offset_w[j*2] + sh_s[p][1] * offset_w[j*2 + 1];
        g_off[((size_t)((b*Hn + y)*Wn + xg))*72 + j] = v;
    }
}

// ---------------------------------------------------------------------------
// Kernel 4: deformable conv implicit GEMM (f32x2, double buffered, coalesced
//           bilinear gather) + relu + fused cls/bbox heads
// ---------------------------------------------------------------------------
__global__ void __launch_bounds__(256, 2)
k_deform(const float* __restrict__ cls_w, const float* __restrict__ cls_b,
         const float* __restrict__ bbox_w, const float* __restrict__ bbox_b,
         float* __restrict__ out) {
    __shared__ float As[2][16*AS_STRIDE];
    __shared__ float Bs[2][16*256];

    const int b  = blockIdx.z;
    const int x0 = blockIdx.x * 16;
    const int y0 = blockIdx.y * 4;
    const int tid = threadIdx.x;
    const int lane = tid & 31;
    const int wg   = tid >> 5;

    const int pA = tid >> 2, laneA = tid & 3;
    const int yP = y0 + (pA >> 4), xP = x0 + (pA & 15);
    const int pixbase = (b*Hn + yP)*Wn + xP;
    const int oB = (tid & 63) * 4, cB = tid >> 6;

    u64 acc[2][16];
    #pragma unroll
    for (int i = 0; i < 2; ++i)
        #pragma unroll
        for (int j = 0; j < 16; ++j) acc[i][j] = 0ull;

    int   ga[4];
    float gw[4];
    float4 a4; float4 b4[4];

    auto calc_meta = [&](int gt) {
        const int g = gt / 9, tap = gt - g*9;
        const int dy = tap/3 - 1, dx = tap%3 - 1;
        const float offy = g_off[(size_t)pixbase*72 + gt*2 + 0];
        const float offx = g_off[(size_t)pixbase*72 + gt*2 + 1];
        const float py  = (float)(yP + dy) + offy;
        const float pxf = (float)(xP + dx) + offx;
        const float y0f = floorf(py), x0f = floorf(pxf);
        const float wy = py - y0f, wx = pxf - x0f;
        const int yi = (int)y0f, xi = (int)x0f;
        #pragma unroll
        for (int cy = 0; cy < 2; ++cy)
            #pragma unroll
            for (int cx = 0; cx < 2; ++cx) {
                const int k = cy*2 + cx;
                const int yc = yi + cy, xc = xi + cx;
                const bool valid = (yc >= 0 && yc < Hn && xc >= 0 && xc < Wn);
                const int ycc = min(max(yc, 0), Hn - 1);
                const int xcc = min(max(xc, 0), Wn - 1);
                const float wv = (cy ? wy : 1.f - wy) * (cx ? wx : 1.f - wx);
                gw[k] = valid ? wv : 0.f;
                ga[k] = ((b*Hn + ycc)*Wn + xcc)*Cn + g*CGn;
            }
    };

    auto fetch = [&](int n) {     // chunk n: gt = n>>2, cin sub-chunk = n&3
        if ((n & 3) == 0) calc_meta(n >> 2);
        const int cc = (n & 3)*16 + laneA*4;
        const float4 v0 = *(const float4*)&g_t[(size_t)ga[0] + cc];
        const float4 v1 = *(const float4*)&g_t[(size_t)ga[1] + cc];
        const float4 v2 = *(const float4*)&g_t[(size_t)ga[2] + cc];
        const float4 v3 = *(const float4*)&g_t[(size_t)ga[3] + cc];
        a4.x = gw[0]*v0.x + gw[1]*v1.x + gw[2]*v2.x + gw[3]*v3.x;
        a4.y = gw[0]*v0.y + gw[1]*v1.y + gw[2]*v2.y + gw[3]*v3.y;
        a4.z = gw[0]*v0.z + gw[1]*v1.z + gw[2]*v2.z + gw[3]*v3.z;
        a4.w = gw[0]*v0.w + gw[1]*v1.w + gw[2]*v2.w + gw[3]*v3.w;
        #pragma unroll
        for (int q = 0; q < 4; ++q)
            b4[q] = *(const float4*)
                &g_w2[(size_t)((n>>2)*64 + (n&3)*16 + cB + q*4)*Cn + oB];
    };

    auto stage = [&](int nb) {
        As[nb][(laneA*4+0)*AS_STRIDE + pA] = a4.x;
        As[nb][(laneA*4+1)*AS_STRIDE + pA] = a4.y;
        As[nb][(laneA*4+2)*AS_STRIDE + pA] = a4.z;
        As[nb][(laneA*4+3)*AS_STRIDE + pA] = a4.w;
        #pragma unroll
        for (int q = 0; q < 4; ++q)
            *(float4*)&Bs[nb][(cB + q*4)*256 + oB] = b4[q];
    };

    fetch(0);
    stage(0);
    __syncthreads();

    for (int kt = 0; kt < 144; ++kt) {
        const int buf = kt & 1;
        if (kt < 143) fetch(kt + 1);

        #pragma unroll
        for (int kk = 0; kk < 16; ++kk) {
            float2 af = *(const float2*)&As[buf][kk*AS_STRIDE + lane*2];
            u64 ad0 = pk2(af.x, af.x);
            u64 ad1 = pk2(af.y, af.y);
            const u64* brow = (const u64*)&Bs[buf][kk*256 + wg*32];
            #pragma unroll
            for (int h = 0; h < 2; ++h) {
                u64 bb[8];
                #pragma unroll
                for (int j = 0; j < 8; ++j) bb[j] = brow[h*8 + j];
                #pragma unroll
                for (int j = 0; j < 8; ++j) {
                    fma2(acc[0][h*8+j], ad0, bb[j]);
                    fma2(acc[1][h*8+j], ad1, bb[j]);
                }
            }
        }

        if (kt < 143) stage((kt + 1) & 1);
        __syncthreads();
    }

    // ---- epilogue: relu + cls/bbox head partials -----------------------
    float pc[2]  = {0.f, 0.f};
    float pb[4][2] = {{0.f,0.f},{0.f,0.f},{0.f,0.f},{0.f,0.f}};

    #pragma unroll
    for (int i = 0; i < 2; ++i)
        #pragma unroll
        for (int j = 0; j < 16; ++j) {
            float xlo, xhi; up2(acc[i][j], xlo, xhi);
            const int oc = wg*32 + 2*j;
            const float v0 = fmaxf(xlo, 0.f);
            const float v1 = fmaxf(xhi, 0.f);
            pc[i]    += v0*cls_w[oc]        + v1*cls_w[oc+1];
            pb[0][i] += v0*bbox_w[oc]       + v1*bbox_w[oc+1];
            pb[1][i] += v0*bbox_w[Cn+oc]    + v1*bbox_w[Cn+oc+1];
            pb[2][i] += v0*bbox_w[2*Cn+oc]  + v1*bbox_w[2*Cn+oc+1];
            pb[3][i] += v0*bbox_w[3*Cn+oc]  + v1*bbox_w[3*Cn+oc+1];
        }

    float* red = &Bs[0][0];   // 8192 floats scratch (loop done)
    #pragma unroll
    for (int i = 0; i < 2; ++i) {
        const int px = lane*2 + i;
        red[0*512 + px*8 + wg] = pc[i];
        #pragma unroll
        for (int h = 0; h < 4; ++h)
            red[(h+1)*512 + px*8 + wg] = pb[h][i];
    }
    __syncthreads();

    if (tid < 64) {
        const int px = tid;
        float s[5] = {0.f, 0.f, 0.f, 0.f, 0.f};
        #pragma unroll
        for (int h = 0; h < 5; ++h)
            #pragma unroll
            for (int w = 0; w < 8; ++w)
                s[h] += red[h*512 + px*8 + w];
        const int y = y0 + (px >> 4), xg = x0 + (px & 15);
        const int pix = y*Wn + xg;
        out[OUT_LOGITS + b*HW + pix]       = s[0] + cls_b[0];
        #pragma unroll
        for (int h = 0; h < 4; ++h)
            out[OUT_BBOX + (b*4 + h)*HW + pix] = s[h+1] + bbox_b[h];
    }
}

// ---------------------------------------------------------------------------
extern "C" void kernel_launch(void* const* d_in, const int* in_sizes, int n_in,
                              void* d_out, int out_size) {
    const float* feature  = (const float*)d_in[0];
    const float* conv_w   = (const float*)d_in[1];
    const float* conv_b   = (const float*)d_in[2];
    const float* loc_w    = (const float*)d_in[3];
    const float* loc_b    = (const float*)d_in[4];
    const float* shape_w  = (const float*)d_in[5];
    const float* shape_b  = (const float*)d_in[6];
    const float* offset_w = (const float*)d_in[7];
    const float* adapt_w  = (const float*)d_in[8];
    const float* cls_w    = (const float*)d_in[9];
    const float* cls_b    = (const float*)d_in[10];
    const float* bbox_w   = (const float*)d_in[11];
    const float* bbox_b   = (const float*)d_in[12];
    float* out = (float*)d_out;

    k_transpose_feat<<<dim3(HW/32, Cn/32, Bn), dim3(32, 8)>>>(feature);
    k_prep_w<<<(2*KKn*Cn*Cn + 255)/256, 256>>>(conv_w, adapt_w);
    k_conv1<<<dim3(Wn/16, Hn/4, Bn), 256>>>(conv_b, loc_w, loc_b,
                                            shape_w, shape_b, offset_w, out);
    k_deform<<<dim3(Wn/16, Hn/4, Bn), 256>>>(cls_w, cls_b, bbox_w, bbox_b, out);
}

// round 5
// speedup vs baseline: 1.6546x; 1.6546x over previous
#include <cuda_runtime.h>
#include <math.h>
#include <stdint.h>

// Problem constants
#define Bn 2
#define Cn 256
#define Hn 96
#define Wn 96
#define HW (Hn*Wn)          // 9216
#define CGn 64
#define KKn 9
#define KTOT 2304
#define NCHUNK 72           // K chunks of 32
#define NTILE 144           // 64-px tiles per batch image

// Output layout (tuple order, each tensor flattened C-order)
#define OUT_LOGITS 0
#define OUT_BBOX   18432
#define OUT_SHAPE  92160
#define OUT_LOC    129024

// GEMM smem strides (floats)
#define LDA 36
#define LDB 36
#define LDD 136

// Dynamic smem byte offsets
#define SM_B_OFF   9216      // A: [0, 9216) = 64*36*4
#define SM_RED     46080     // B: [9216, 46080) = 256*36*4 ; red <= 5*64*4*4
#define SM_SHV     51200
#define SM_TOTAL   51712

// Scratch (device globals; no dynamic allocation allowed)
__device__ float g_x   [Bn*HW*Cn];     // feature NHWC (tf32-rounded)
__device__ float g_t   [Bn*HW*Cn];     // conv1 output NHWC (fp32)
__device__ float g_off [Bn*HW*72];     // per-pixel offsets
__device__ float g_w1tc[KTOT*Cn];      // conv_w  chunked [chunk][oc][32], tf32
__device__ float g_w2tc[KTOT*Cn];      // adapt_w chunked [chunk][oc][32], tf32

// ---------------- helpers ---------------------------------------------------
__device__ __forceinline__ uint32_t smem_u32(const void* p) {
    uint32_t a;
    asm("{ .reg .u64 t; cvta.to.shared.u64 t, %1; cvt.u32.u64 %0, t; }"
        : "=r"(a) : "l"(p));
    return a;
}
__device__ __forceinline__ float tf32r(float x) {
    uint32_t u;
    asm("cvt.rna.tf32.f32 %0, %1;" : "=r"(u) : "f"(x));
    return __uint_as_float(u);
}
__device__ __forceinline__ void mma8(float* d, const uint32_t* a,
                                     uint32_t b0, uint32_t b1) {
    asm volatile(
        "mma.sync.aligned.m16n8k8.row.col.f32.tf32.tf32.f32 "
        "{%0,%1,%2,%3},{%4,%5,%6,%7},{%8,%9},{%0,%1,%2,%3};"
        : "+f"(d[0]), "+f"(d[1]), "+f"(d[2]), "+f"(d[3])
        : "r"(a[0]), "r"(a[1]), "r"(a[2]), "r"(a[3]), "r"(b0), "r"(b1));
}
#define CPA16(dst, src) \
    asm volatile("cp.async.ca.shared.global [%0], [%1], 16;" \
                 :: "r"(dst), "l"(src))
#define CPA16Z(dst, src, n) \
    asm volatile("cp.async.ca.shared.global [%0], [%1], 16, %2;" \
                 :: "r"(dst), "l"(src), "r"(n))
#define CPA_COMMIT() asm volatile("cp.async.commit_group;")
#define CPA_WAIT0()  asm volatile("cp.async.wait_group 0;")

// ---------------------------------------------------------------------------
// Kernel 1: NCHW -> NHWC transpose of feature, tf32-rounded
// ---------------------------------------------------------------------------
__global__ void k_transpose_feat(const float* __restrict__ x) {
    __shared__ float tile[32][33];
    int b  = blockIdx.z;
    int p0 = blockIdx.x * 32;
    int c0 = blockIdx.y * 32;
    int txi = threadIdx.x, tyi = threadIdx.y;  // 32 x 8
    #pragma unroll
    for (int s = 0; s < 32; s += 8)
        tile[tyi + s][txi] = x[(size_t)(b*Cn + c0 + tyi + s)*HW + p0 + txi];
    __syncthreads();
    #pragma unroll
    for (int s = 0; s < 32; s += 8)
        g_x[(size_t)(b*HW + p0 + tyi + s)*Cn + c0 + txi] = tf32r(tile[txi][tyi + s]);
}

// ---------------------------------------------------------------------------
// Kernel 2: weight re-layout into chunked [chunk][oc][32] tf32 tiles
// ---------------------------------------------------------------------------
__global__ void k_prep_w(const float* __restrict__ conv_w,
                         const float* __restrict__ adapt_w) {
    const int n = KTOT*Cn;  // 589824
    int idx = blockIdx.x * blockDim.x + threadIdx.x;
    if (idx < n) {
        int dk = idx & 31;
        int o  = (idx >> 5) & 255;
        int ch = idx >> 13;          // 0..71
        int tap = ch >> 3;
        int c   = (ch & 7)*32 + dk;
        g_w1tc[idx] = tf32r(conv_w[(o*Cn + c)*KKn + tap]);
    } else if (idx < 2*n) {
        int j  = idx - n;
        int dk = j & 31;
        int o  = (j >> 5) & 255;
        int ch = j >> 13;            // 0..71
        int gt = ch >> 1;
        int ci = (ch & 1)*32 + dk;
        int g  = gt / 9, tap = gt % 9;
        g_w2tc[j] = tf32r(adapt_w[(o*Cn + g*CGn + ci)*KKn + tap]);
    }
}

// ---------------------------------------------------------------------------
// Kernel 3: conv3x3 via mma.sync tf32, fused bias/relu/loc/shape/offsets
// Grid: (NTILE, Bn) = (144, 2). Block 256 (8 warps: 2m x 4n).
// ---------------------------------------------------------------------------
__global__ void __launch_bounds__(256, 2)
k_conv1_mma(const float* __restrict__ conv_b_,
            const float* __restrict__ loc_w,  const float* __restrict__ loc_b,
            const float* __restrict__ shape_w,const float* __restrict__ shape_b,
            const float* __restrict__ offset_w,
            float* __restrict__ out) {
    extern __shared__ __align__(128) char smem[];
    float* Asm = (float*)smem;
    float* Bsm = (float*)(smem + SM_B_OFF);
    float* Dsm = Bsm;                         // reuse after GEMM
    float* red = (float*)(smem + SM_RED);
    float* shv = (float*)(smem + SM_SHV);
    const uint32_t sA = smem_u32(Asm), sB = smem_u32(Bsm);

    const int tid = threadIdx.x, wid = tid >> 5, lane = tid & 31;
    const int g = lane >> 2, t = lane & 3;
    const int wm = wid & 1, wn = wid >> 1;

    const int tt = blockIdx.x;
    const int b  = blockIdx.y;
    const int y0 = (tt / 6) * 4, x0 = (tt % 6) * 16;

    // staging mapping: px = tid>>2 (64), qS = tid&3 (8 ch each)
    const int pS = tid >> 2, qS = tid & 3;
    const int ySr = pS >> 4, xSc = pS & 15;

    float d[2][8][4];
    #pragma unroll
    for (int i = 0; i < 2; ++i)
        #pragma unroll
        for (int j = 0; j < 8; ++j)
            #pragma unroll
            for (int k = 0; k < 4; ++k) d[i][j][k] = 0.f;

    const uint32_t da = sA + (uint32_t)(pS*LDA + qS*8)*4;
    const uint32_t db = sB + (uint32_t)(tid*LDB)*4;

    for (int c = 0; c < NCHUNK; ++c) {
        const int tap = c >> 3, cin0 = (c & 7) << 5;
        const int dy = tap/3 - 1, dx = tap%3 - 1;
        const int yy = y0 + ySr + dy, xx = x0 + xSc + dx;
        const bool ok = (yy >= 0 && yy < Hn && xx >= 0 && xx < Wn);
        const float* src = ok
            ? &g_x[((size_t)((b*Hn + yy)*Wn + xx))*Cn + cin0 + qS*8] : g_x;
        const uint32_t nbytes = ok ? 16u : 0u;
        CPA16Z(da,      src,     nbytes);
        CPA16Z(da + 16, src + 4, nbytes);
        const float* ws = &g_w1tc[(size_t)c*8192 + tid*32];
        #pragma unroll
        for (int q = 0; q < 8; ++q) CPA16(db + q*16, ws + q*4);
        CPA_COMMIT();
        CPA_WAIT0();
        __syncthreads();

        #pragma unroll
        for (int ks = 0; ks < 4; ++ks) {
            const int k0 = ks*8;
            uint32_t a[2][4];
            #pragma unroll
            for (int ma = 0; ma < 2; ++ma) {
                const float* ap = &Asm[(wm*32 + ma*16 + g)*LDA + k0 + t];
                a[ma][0] = __float_as_uint(ap[0]);
                a[ma][1] = __float_as_uint(ap[8*LDA]);
                a[ma][2] = __float_as_uint(ap[4]);
                a[ma][3] = __float_as_uint(ap[8*LDA + 4]);
            }
            #pragma unroll
            for (int na = 0; na < 8; ++na) {
                const float* bp = &Bsm[(wn*64 + na*8 + g)*LDB + k0 + t];
                const uint32_t b0 = __float_as_uint(bp[0]);
                const uint32_t b1 = __float_as_uint(bp[4]);
                mma8(d[0][na], a[0], b0, b1);
                mma8(d[1][na], a[1], b0, b1);
            }
        }
        __syncthreads();
    }

    // ---- epilogue: bias + relu in place, head partials -----------------
    float P0[4], P1[4], P2[4];
    #pragma unroll
    for (int s = 0; s < 4; ++s) { P0[s] = 0.f; P1[s] = 0.f; P2[s] = 0.f; }

    #pragma unroll
    for (int ma = 0; ma < 2; ++ma)
        #pragma unroll
        for (int na = 0; na < 8; ++na)
            #pragma unroll
            for (int ci = 0; ci < 4; ++ci) {
                const int oc = wn*64 + na*8 + 2*t + (ci & 1);
                const int slot = ma*2 + (ci >> 1);
                float v = fmaxf(d[ma][na][ci] + conv_b_[oc], 0.f);
                d[ma][na][ci] = v;
                P0[slot] += v * loc_w[oc];
                P1[slot] += v * shape_w[oc];
                P2[slot] += v * shape_w[Cn + oc];
            }
    #pragma unroll
    for (int s = 0; s < 4; ++s) {
        P0[s] += __shfl_xor_sync(0xffffffffu, P0[s], 1);
        P0[s] += __shfl_xor_sync(0xffffffffu, P0[s], 2);
        P1[s] += __shfl_xor_sync(0xffffffffu, P1[s], 1);
        P1[s] += __shfl_xor_sync(0xffffffffu, P1[s], 2);
        P2[s] += __shfl_xor_sync(0xffffffffu, P2[s], 2);
        P2[s] += __shfl_xor_sync(0xffffffffu, P2[s], 1);
    }
    if (t == 0) {
        #pragma unroll
        for (int s = 0; s < 4; ++s) {
            const int row = wm*32 + (s >> 1)*16 + g + (s & 1)*8;
            red[0*256 + row*4 + wn] = P0[s];
            red[1*256 + row*4 + wn] = P1[s];
            red[2*256 + row*4 + wn] = P2[s];
        }
    }
    __syncthreads();

    if (tid < 64) {
        const int px = tid;
        float sl = 0.f, s0 = 0.f, s1 = 0.f;
        #pragma unroll
        for (int w = 0; w < 4; ++w) {
            sl += red[0*256 + px*4 + w];
            s0 += red[1*256 + px*4 + w];
            s1 += red[2*256 + px*4 + w];
        }
        const int y = y0 + (px >> 4), xg = x0 + (px & 15);
        const int pix = y*Wn + xg;
        out[OUT_LOC + b*HW + pix] = sl + loc_b[0];
        const float a0 = s0 + shape_b[0];
        const float a1 = s1 + shape_b[1];
        out[OUT_SHAPE + (b*2 + 0)*HW + pix] = a0;
        out[OUT_SHAPE + (b*2 + 1)*HW + pix] = a1;
        shv[px*2 + 0] = a0;
        shv[px*2 + 1] = a1;
    }
    __syncthreads();

    // offsets: 64 px x 72 ch
    for (int idx = tid; idx < 64*72; idx += 256) {
        const int p = idx / 72, j = idx % 72;
        const int y = y0 + (p >> 4), xg = x0 + (p & 15);
        float v = shv[p*2]*offset_w[j*2] + shv[p*2+1]*offset_w[j*2+1];
        g_off[((size_t)((b*Hn + y)*Wn + xg))*72 + j] = v;
    }

    // g_t staging through smem (2 oc halves) for coalesced stores
    const int pixS = (b*Hn + y0 + ySr)*Wn + x0 + xSc;
    #pragma unroll
    for (int h = 0; h < 2; ++h) {
        __syncthreads();
        if ((wn >> 1) == h) {
            #pragma unroll
            for (int ma = 0; ma < 2; ++ma)
                #pragma unroll
                for (int na = 0; na < 8; ++na)
                    #pragma unroll
                    for (int ci = 0; ci < 4; ++ci) {
                        const int row = wm*32 + ma*16 + g + (ci >> 1)*8;
                        const int col = (wn & 1)*64 + na*8 + 2*t + (ci & 1);
                        Dsm[row*LDD + col] = d[ma][na][ci];
                    }
        }
        __syncthreads();
        #pragma unroll
        for (int j = 0; j < 8; ++j) {
            float4 v = *(const float4*)&Dsm[pS*LDD + qS*32 + j*4];
            *(float4*)&g_t[(size_t)pixS*Cn + h*128 + qS*32 + j*4] = v;
        }
    }
}

// ---------------------------------------------------------------------------
// Kernel 4: deformable conv via mma.sync tf32, fused relu/cls/bbox
// ---------------------------------------------------------------------------
__global__ void __launch_bounds__(256, 2)
k_deform_mma(const float* __restrict__ cls_w, const float* __restrict__ cls_b,
             const float* __restrict__ bbox_w, const float* __restrict__ bbox_b,
             float* __restrict__ out) {
    extern __shared__ __align__(128) char smem[];
    float* Asm = (float*)smem;
    float* Bsm = (float*)(smem + SM_B_OFF);
    float* red = (float*)(smem + SM_RED);
    const uint32_t sB = smem_u32(Bsm);

    const int tid = threadIdx.x, wid = tid >> 5, lane = tid & 31;
    const int g = lane >> 2, t = lane & 3;
    const int wm = wid & 1, wn = wid >> 1;

    const int tt = blockIdx.x;
    const int b  = blockIdx.y;
    const int y0 = (tt / 6) * 4, x0 = (tt % 6) * 16;

    const int pS = tid >> 2, qS = tid & 3;
    const int yP = y0 + (pS >> 4), xP = x0 + (pS & 15);
    const int pixb = (b*Hn + yP)*Wn + xP;

    float d[2][8][4];
    #pragma unroll
    for (int i = 0; i < 2; ++i)
        #pragma unroll
        for (int j = 0; j < 8; ++j)
            #pragma unroll
            for (int k = 0; k < 4; ++k) d[i][j][k] = 0.f;

    const uint32_t db = sB + (uint32_t)(tid*LDB)*4;
    int   ga[4];
    float gw[4];

    for (int c = 0; c < NCHUNK; ++c) {
        // B weights via cp.async (overlaps the gather below)
        const float* ws = &g_w2tc[(size_t)c*8192 + tid*32];
        #pragma unroll
        for (int q = 0; q < 8; ++q) CPA16(db + q*16, ws + q*4);
        CPA_COMMIT();

        const int gt = c >> 1, ci0 = (c & 1) * 32;
        if ((c & 1) == 0) {
            const int gg = gt / 9, tap = gt - gg*9;
            const int dy = tap/3 - 1, dx = tap%3 - 1;
            const float offy = g_off[(size_t)pixb*72 + gt*2 + 0];
            const float offx = g_off[(size_t)pixb*72 + gt*2 + 1];
            const float pyf = (float)(yP + dy) + offy;
            const float pxf = (float)(xP + dx) + offx;
            const float y0f = floorf(pyf), x0f = floorf(pxf);
            const float wy = pyf - y0f, wx = pxf - x0f;
            const int yi = (int)y0f, xi = (int)x0f;
            #pragma unroll
            for (int cy = 0; cy < 2; ++cy)
                #pragma unroll
                for (int cx = 0; cx < 2; ++cx) {
                    const int k = cy*2 + cx;
                    const int yc = yi + cy, xc = xi + cx;
                    const bool valid = (yc >= 0 && yc < Hn && xc >= 0 && xc < Wn);
                    const int ycc = min(max(yc, 0), Hn - 1);
                    const int xcc = min(max(xc, 0), Wn - 1);
                    const float wv = (cy ? wy : 1.f - wy) * (cx ? wx : 1.f - wx);
                    gw[k] = valid ? wv : 0.f;
                    ga[k] = ((b*Hn + ycc)*Wn + xcc)*Cn + gg*CGn;
                }
        }
        // bilinear gather -> A tile (8 ch per thread), tf32-rounded
        {
            const int chb = ci0 + qS*8;
            float4 r0, r1;
            const float4 u00 = *(const float4*)&g_t[(size_t)ga[0] + chb];
            const float4 u01 = *(const float4*)&g_t[(size_t)ga[0] + chb + 4];
            const float4 u10 = *(const float4*)&g_t[(size_t)ga[1] + chb];
            const float4 u11 = *(const float4*)&g_t[(size_t)ga[1] + chb + 4];
            const float4 u20 = *(const float4*)&g_t[(size_t)ga[2] + chb];
            const float4 u21 = *(const float4*)&g_t[(size_t)ga[2] + chb + 4];
            const float4 u30 = *(const float4*)&g_t[(size_t)ga[3] + chb];
            const float4 u31 = *(const float4*)&g_t[(size_t)ga[3] + chb + 4];
            r0.x = tf32r(gw[0]*u00.x + gw[1]*u10.x + gw[2]*u20.x + gw[3]*u30.x);
            r0.y = tf32r(gw[0]*u00.y + gw[1]*u10.y + gw[2]*u20.y + gw[3]*u30.y);
            r0.z = tf32r(gw[0]*u00.z + gw[1]*u10.z + gw[2]*u20.z + gw[3]*u30.z);
            r0.w = tf32r(gw[0]*u00.w + gw[1]*u10.w + gw[2]*u20.w + gw[3]*u30.w);
            r1.x = tf32r(gw[0]*u01.x + gw[1]*u11.x + gw[2]*u21.x + gw[3]*u31.x);
            r1.y = tf32r(gw[0]*u01.y + gw[1]*u11.y + gw[2]*u21.y + gw[3]*u31.y);
            r1.z = tf32r(gw[0]*u01.z + gw[1]*u11.z + gw[2]*u21.z + gw[3]*u31.z);
            r1.w = tf32r(gw[0]*u01.w + gw[1]*u11.w + gw[2]*u21.w + gw[3]*u31.w);
            *(float4*)&Asm[pS*LDA + qS*8]     = r0;
            *(float4*)&Asm[pS*LDA + qS*8 + 4] = r1;
        }
        CPA_WAIT0();
        __syncthreads();

        #pragma unroll
        for (int ks = 0; ks < 4; ++ks) {
            const int k0 = ks*8;
            uint32_t a[2][4];
            #pragma unroll
            for (int ma = 0; ma < 2; ++ma) {
                const float* ap = &Asm[(wm*32 + ma*16 + g)*LDA + k0 + t];
                a[ma][0] = __float_as_uint(ap[0]);
                a[ma][1] = __float_as_uint(ap[8*LDA]);
                a[ma][2] = __float_as_uint(ap[4]);
                a[ma][3] = __float_as_uint(ap[8*LDA + 4]);
            }
            #pragma unroll
            for (int na = 0; na < 8; ++na) {
                const float* bp = &Bsm[(wn*64 + na*8 + g)*LDB + k0 + t];
                const uint32_t b0 = __float_as_uint(bp[0]);
                const uint32_t b1 = __float_as_uint(bp[4]);
                mma8(d[0][na], a[0], b0, b1);
                mma8(d[1][na], a[1], b0, b1);
            }
        }
        __syncthreads();
    }

    // ---- epilogue: relu + cls/bbox head partials -----------------------
    float P[5][4];
    #pragma unroll
    for (int h = 0; h < 5; ++h)
        #pragma unroll
        for (int s = 0; s < 4; ++s) P[h][s] = 0.f;

    #pragma unroll
    for (int ma = 0; ma < 2; ++ma)
        #pragma unroll
        for (int na = 0; na < 8; ++na)
            #pragma unroll
            for (int ci = 0; ci < 4; ++ci) {
                const int oc = wn*64 + na*8 + 2*t + (ci & 1);
                const int slot = ma*2 + (ci >> 1);
                const float v = fmaxf(d[ma][na][ci], 0.f);
                P[0][slot] += v * cls_w[oc];
                P[1][slot] += v * bbox_w[oc];
                P[2][slot] += v * bbox_w[Cn + oc];
                P[3][slot] += v * bbox_w[2*Cn + oc];
                P[4][slot] += v * bbox_w[3*Cn + oc];
            }
    #pragma unroll
    for (int h = 0; h < 5; ++h)
        #pragma unroll
        for (int s = 0; s < 4; ++s) {
            P[h][s] += __shfl_xor_sync(0xffffffffu, P[h][s], 1);
            P[h][s] += __shfl_xor_sync(0xffffffffu, P[h][s], 2);
        }
    if (t == 0) {
        #pragma unroll
        for (int s = 0; s < 4; ++s) {
            const int row = wm*32 + (s >> 1)*16 + g + (s & 1)*8;
            #pragma unroll
            for (int h = 0; h < 5; ++h)
                red[h*256 + row*4 + wn] = P[h][s];
        }
    }
    __syncthreads();

    if (tid < 64) {
        const int px = tid;
        float s[5] = {0.f, 0.f, 0.f, 0.f, 0.f};
        #pragma unroll
        for (int h = 0; h < 5; ++h)
            #pragma unroll
            for (int w = 0; w < 4; ++w)
                s[h] += red[h*256 + px*4 + w];
        const int y = y0 + (px >> 4), xg = x0 + (px & 15);
        const int pix = y*Wn + xg;
        out[OUT_LOGITS + b*HW + pix]        = s[0] + cls_b[0];
        out[OUT_BBOX + (b*4 + 0)*HW + pix]  = s[1] + bbox_b[0];
        out[OUT_BBOX + (b*4 + 1)*HW + pix]  = s[2] + bbox_b[1];
        out[OUT_BBOX + (b*4 + 2)*HW + pix]  = s[3] + bbox_b[2];
        out[OUT_BBOX + (b*4 + 3)*HW + pix]  = s[4] + bbox_b[3];
    }
}

// ---------------------------------------------------------------------------
extern "C" void kernel_launch(void* const* d_in, const int* in_sizes, int n_in,
                              void* d_out, int out_size) {
    const float* feature  = (const float*)d_in[0];
    const float* conv_w   = (const float*)d_in[1];
    const float* conv_b   = (const float*)d_in[2];
    const float* loc_w    = (const float*)d_in[3];
    const float* loc_b    = (const float*)d_in[4];
    const float* shape_w  = (const float*)d_in[5];
    const float* shape_b  = (const float*)d_in[6];
    const float* offset_w = (const float*)d_in[7];
    const float* adapt_w  = (const float*)d_in[8];
    const float* cls_w    = (const float*)d_in[9];
    const float* cls_b    = (const float*)d_in[10];
    const float* bbox_w   = (const float*)d_in[11];
    const float* bbox_b   = (const float*)d_in[12];
    float* out = (float*)d_out;

    cudaFuncSetAttribute(k_conv1_mma,
        cudaFuncAttributeMaxDynamicSharedMemorySize, SM_TOTAL);
    cudaFuncSetAttribute(k_deform_mma,
        cudaFuncAttributeMaxDynamicSharedMemorySize, SM_TOTAL);

    k_transpose_feat<<<dim3(HW/32, Cn/32, Bn), dim3(32, 8)>>>(feature);
    k_prep_w<<<(2*KTOT*Cn + 255)/256, 256>>>(conv_w, adapt_w);
    k_conv1_mma<<<dim3(NTILE, Bn), 256, SM_TOTAL>>>(conv_b, loc_w, loc_b,
                                                    shape_w, shape_b,
                                                    offset_w, out);
    k_deform_mma<<<dim3(NTILE, Bn), 256, SM_TOTAL>>>(cls_w, cls_b,
                                                     bbox_w, bbox_b, out);
}